// round 15
// baseline (speedup 1.0000x reference)
#include <cuda_runtime.h>
#include <cuda_bf16.h>
#include <math.h>

#define NR   8192     // rows of z
#define HD   256      // feature dim
#define NC   64       // clusters
#define RPB  64       // rows per block
#define TPB  512      // 16 warps: 4 warp_m x 4 warp_n, warp tile m16n16
#define NBLK (NR / RPB)   // 128 blocks, one wave, 1 block/SM

// bf16 tiles [64][256], row stride 512B, XOR-swizzled; 32KB each
#define OFF_Z  0
#define OFF_C  32768
#define SMEM_B 65536

#define FXSCALE 4294967296.0f          // 2^32
#define FXINV   (1.0f / 4294967296.0f)

__device__ unsigned long long g_colfx[2][NC]; // fixed-point colsums, epoch-parity buffered
__device__ unsigned int g_start;      // start ticket counter (epoch source)
__device__ unsigned int g_arrive;     // arrival ticket counter (grid sync)

#define LDSM4(r, addr) \
    asm volatile("ldmatrix.sync.aligned.m8n8.x4.shared.b16 {%0,%1,%2,%3}, [%4];" \
        : "=r"((r)[0]), "=r"((r)[1]), "=r"((r)[2]), "=r"((r)[3]) : "r"(addr))

#define MMA16816(d, a, b0, b1) \
    asm volatile("mma.sync.aligned.m16n8k16.row.col.f32.bf16.bf16.f32 " \
        "{%0,%1,%2,%3},{%4,%5,%6,%7},{%8,%9},{%0,%1,%2,%3};" \
        : "+f"((d)[0]), "+f"((d)[1]), "+f"((d)[2]), "+f"((d)[3]) \
        : "r"((a)[0]), "r"((a)[1]), "r"((a)[2]), "r"((a)[3]), "r"(b0), "r"(b1))

__device__ __forceinline__ unsigned bf2_bits(__nv_bfloat162 h) {
    return *reinterpret_cast<unsigned*>(&h);
}
__device__ __forceinline__ float fsqrt_ap(float x) {
    float r; asm("sqrt.approx.ftz.f32 %0, %1;" : "=f"(r) : "f"(x)); return r;
}
__device__ __forceinline__ float frcp_ap(float x) {
    float r; asm("rcp.approx.ftz.f32 %0, %1;" : "=f"(r) : "f"(x)); return r;
}

__global__ void __launch_bounds__(TPB, 1)
fused_kernel(const float* __restrict__ z, const float* __restrict__ cent,
             float* __restrict__ Q, float* __restrict__ P) {
    extern __shared__ char smem[];
    char* zt = smem + OFF_Z;
    char* ct = smem + OFF_C;
    __shared__ float s_zn[RPB], s_cn[NC];
    __shared__ float s_rsp[4][RPB];    // staged row-sum partials (per wn warp-col)
    __shared__ float s_ct[NC];         // colsum reciprocals
    __shared__ unsigned s_epoch;

    const int t = threadIdx.x;
    const unsigned sb = (unsigned)__cvta_generic_to_shared(smem);

    // epoch from monotonic start ticket (same value across all blocks of a launch)
    if (t == 0) {
        unsigned st = atomicAdd(&g_start, 1u);
        s_epoch = st / NBLK;
    }

    // ---- Phase 1: issue ALL 16 LDG.128 up front (z + centroids), then convert ----
    {
        const int row = t >> 3;
        const int l8 = t & 7;
        const float4* zg = (const float4*)(z + (size_t)blockIdx.x * RPB * HD);
        const float4* cg = (const float4*)cent;

        float4 vz[8], vc[8];
        #pragma unroll
        for (int j = 0; j < 8; j++) vz[j] = zg[row * (HD / 4) + (l8 + 8 * j)];
        #pragma unroll
        for (int j = 0; j < 8; j++) vc[j] = cg[row * (HD / 4) + (l8 + 8 * j)];

        float az = 0.f, ac = 0.f;
        #pragma unroll
        for (int j = 0; j < 8; j++) {
            const int c4 = l8 + 8 * j;
            const int byteoff = 8 * c4;
            const unsigned off = row * 512 +
                ((((byteoff >> 4) ^ (row & 7)) << 4) | (byteoff & 15));

            az = fmaf(vz[j].x, vz[j].x, az);
            az = fmaf(vz[j].y, vz[j].y, az);
            az = fmaf(vz[j].z, vz[j].z, az);
            az = fmaf(vz[j].w, vz[j].w, az);
            __nv_bfloat162 zh01 = __floats2bfloat162_rn(vz[j].x, vz[j].y);
            __nv_bfloat162 zh23 = __floats2bfloat162_rn(vz[j].z, vz[j].w);
            *(uint2*)(zt + off) = make_uint2(bf2_bits(zh01), bf2_bits(zh23));

            ac = fmaf(vc[j].x, vc[j].x, ac);
            ac = fmaf(vc[j].y, vc[j].y, ac);
            ac = fmaf(vc[j].z, vc[j].z, ac);
            ac = fmaf(vc[j].w, vc[j].w, ac);
            __nv_bfloat162 ch01 = __floats2bfloat162_rn(vc[j].x, vc[j].y);
            __nv_bfloat162 ch23 = __floats2bfloat162_rn(vc[j].z, vc[j].w);
            *(uint2*)(ct + off) = make_uint2(bf2_bits(ch01), bf2_bits(ch23));
        }
        az += __shfl_xor_sync(0xffffffffu, az, 1);
        az += __shfl_xor_sync(0xffffffffu, az, 2);
        az += __shfl_xor_sync(0xffffffffu, az, 4);
        ac += __shfl_xor_sync(0xffffffffu, ac, 1);
        ac += __shfl_xor_sync(0xffffffffu, ac, 2);
        ac += __shfl_xor_sync(0xffffffffu, ac, 4);
        if (l8 == 0) { s_zn[row] = az; s_cn[row] = ac; }
    }
    __syncthreads();   // BAR A

    // ---- Phase 2: bf16 GEMM mainloop (single-term), warp m16n16, k16/step ----
    const int lane = t & 31, wid = t >> 5;
    const int wm = wid >> 2, wn = wid & 3;
    const int tile = lane >> 3, rit = lane & 7;

    const int arow = wm * 16 + rit + 8 * (tile & 1);
    const int acb = tile >> 1;
    const unsigned abase = sb + OFF_Z + arow * 512;
    const int axor = arow & 7;

    const int brow = wn * 16 + rit + 8 * (tile >> 1);
    const int bcb = tile & 1;
    const unsigned bbase = sb + OFF_C + brow * 512;
    const int bxor = brow & 7;

    float d0[4] = {0.f, 0.f, 0.f, 0.f};   // n-half 0
    float d1[4] = {0.f, 0.f, 0.f, 0.f};   // n-half 1

    #pragma unroll
    for (int ks = 0; ks < 16; ks++) {
        const unsigned aoff = (unsigned)(((2 * ks + acb) ^ axor) << 4);
        const unsigned boff = (unsigned)(((2 * ks + bcb) ^ bxor) << 4);
        unsigned a[4], b[4];
        LDSM4(a, abase + aoff);
        LDSM4(b, bbase + boff);
        MMA16816(d0, a, b[0], b[1]);
        MMA16816(d1, a, b[2], b[3]);
    }

    // ---- Phase 3: epilogue -> Q ----
    const int gid = lane >> 2, tig = lane & 3;
    const int R0 = wm * 16 + gid, R1 = R0 + 8;
    const float znA = s_zn[R0], znB = s_zn[R1];
    const int c00 = wn * 16 + 2 * tig;
    const int c10 = c00 + 8;
    const float cnA0 = s_cn[c00], cnA1 = s_cn[c00 + 1];
    const float cnB0 = s_cn[c10], cnB1 = s_cn[c10 + 1];

    float q00 = frcp_ap(1.f + fsqrt_ap(fmaxf(fmaf(-2.f, d0[0], znA + cnA0), 0.f)));
    float q01 = frcp_ap(1.f + fsqrt_ap(fmaxf(fmaf(-2.f, d0[1], znA + cnA1), 0.f)));
    float q02 = frcp_ap(1.f + fsqrt_ap(fmaxf(fmaf(-2.f, d0[2], znB + cnA0), 0.f)));
    float q03 = frcp_ap(1.f + fsqrt_ap(fmaxf(fmaf(-2.f, d0[3], znB + cnA1), 0.f)));
    float q10 = frcp_ap(1.f + fsqrt_ap(fmaxf(fmaf(-2.f, d1[0], znA + cnB0), 0.f)));
    float q11 = frcp_ap(1.f + fsqrt_ap(fmaxf(fmaf(-2.f, d1[1], znA + cnB1), 0.f)));
    float q12 = frcp_ap(1.f + fsqrt_ap(fmaxf(fmaf(-2.f, d1[2], znB + cnB0), 0.f)));
    float q13 = frcp_ap(1.f + fsqrt_ap(fmaxf(fmaf(-2.f, d1[3], znB + cnB1), 0.f)));

    // row sums: shfl over tig lanes, then staged STS (no atomics)
    float rs0 = (q00 + q01) + (q10 + q11);
    float rs1 = (q02 + q03) + (q12 + q13);
    rs0 += __shfl_xor_sync(0xffffffffu, rs0, 1);
    rs0 += __shfl_xor_sync(0xffffffffu, rs0, 2);
    rs1 += __shfl_xor_sync(0xffffffffu, rs1, 1);
    rs1 += __shfl_xor_sync(0xffffffffu, rs1, 2);
    if (tig == 0) { s_rsp[wn][R0] = rs0; s_rsp[wn][R1] = rs1; }
    __syncthreads();   // BAR B

    const float ir0 = frcp_ap(((s_rsp[0][R0] + s_rsp[1][R0]) +
                               (s_rsp[2][R0] + s_rsp[3][R0])));
    const float ir1 = frcp_ap(((s_rsp[0][R1] + s_rsp[1][R1]) +
                               (s_rsp[2][R1] + s_rsp[3][R1])));
    q00 *= ir0; q01 *= ir0; q10 *= ir0; q11 *= ir0;
    q02 *= ir1; q03 *= ir1; q12 *= ir1; q13 *= ir1;

    const int gA = blockIdx.x * RPB + R0;
    const int gB = blockIdx.x * RPB + R1;
    *(float2*)(Q + (size_t)gA * NC + c00) = make_float2(q00, q01);
    *(float2*)(Q + (size_t)gB * NC + c00) = make_float2(q02, q03);
    *(float2*)(Q + (size_t)gA * NC + c10) = make_float2(q10, q11);
    *(float2*)(Q + (size_t)gB * NC + c10) = make_float2(q12, q13);

    // column sums: shfl over gid lanes -> per-warp partials published DIRECTLY
    // as fixed-point atomics (order-independent, deterministic). No smem stage.
    const unsigned buf = s_epoch & 1u;
    float cA0 = q00 + q02, cA1 = q01 + q03;
    float cB0 = q10 + q12, cB1 = q11 + q13;
    #pragma unroll
    for (int m = 4; m <= 16; m <<= 1) {
        cA0 += __shfl_xor_sync(0xffffffffu, cA0, m);
        cA1 += __shfl_xor_sync(0xffffffffu, cA1, m);
        cB0 += __shfl_xor_sync(0xffffffffu, cB0, m);
        cB1 += __shfl_xor_sync(0xffffffffu, cB1, m);
    }
    if (lane < 4) {
        atomicAdd(&g_colfx[buf][c00],     (unsigned long long)llrintf(cA0 * FXSCALE));
        atomicAdd(&g_colfx[buf][c00 + 1], (unsigned long long)llrintf(cA1 * FXSCALE));
        atomicAdd(&g_colfx[buf][c10],     (unsigned long long)llrintf(cB0 * FXSCALE));
        atomicAdd(&g_colfx[buf][c10 + 1], (unsigned long long)llrintf(cB1 * FXSCALE));
    }
    __syncthreads();   // BAR D: all warps' publishes done before t0's release-arrive

    // ---- single-wave grid sync (epoch ticket; release/acquire ordering) ----
    if (t == 0) {
        unsigned ticket;
        asm volatile("atom.global.add.release.gpu.u32 %0, [%1], 1;"
                     : "=r"(ticket) : "l"(&g_arrive) : "memory");
        const unsigned target = (ticket / NBLK + 1u) * NBLK;
        unsigned v;
        do {
            asm volatile("ld.global.acquire.gpu.u32 %0, [%1];"
                         : "=r"(v) : "l"(&g_arrive) : "memory");
        } while (v < target);
    }
    __syncthreads();   // BAR E

    // read final colsums (512B) -> reciprocals; zero other buffer off hot path
    if (t < NC) {
        unsigned long long v = __ldcg(&g_colfx[buf][t]);
        s_ct[t] = frcp_ap((float)v * FXINV);
        g_colfx[buf ^ 1u][t] = 0ull;   // prepare next launch's buffer (idempotent)
    }
    __syncthreads();   // BAR F

    // ---- Phase 4: P from in-register Q ----
    const float icA0 = s_ct[c00], icA1 = s_ct[c00 + 1];
    const float icB0 = s_ct[c10], icB1 = s_ct[c10 + 1];

    float p00 = q00 * q00 * icA0, p01 = q01 * q01 * icA1;
    float p02 = q02 * q02 * icA0, p03 = q03 * q03 * icA1;
    float p10 = q10 * q10 * icB0, p11 = q11 * q11 * icB1;
    float p12 = q12 * q12 * icB0, p13 = q13 * q13 * icB1;

    float ps0 = (p00 + p01) + (p10 + p11);
    float ps1 = (p02 + p03) + (p12 + p13);
    ps0 += __shfl_xor_sync(0xffffffffu, ps0, 1);
    ps0 += __shfl_xor_sync(0xffffffffu, ps0, 2);
    ps1 += __shfl_xor_sync(0xffffffffu, ps1, 1);
    ps1 += __shfl_xor_sync(0xffffffffu, ps1, 2);
    if (tig == 0) { s_rsp[wn][R0] = ps0; s_rsp[wn][R1] = ps1; }
    __syncthreads();   // BAR G

    const float ip0 = frcp_ap(((s_rsp[0][R0] + s_rsp[1][R0]) +
                               (s_rsp[2][R0] + s_rsp[3][R0])));
    const float ip1 = frcp_ap(((s_rsp[0][R1] + s_rsp[1][R1]) +
                               (s_rsp[2][R1] + s_rsp[3][R1])));
    *(float2*)(P + (size_t)gA * NC + c00) = make_float2(p00 * ip0, p01 * ip0);
    *(float2*)(P + (size_t)gB * NC + c00) = make_float2(p02 * ip1, p03 * ip1);
    *(float2*)(P + (size_t)gA * NC + c10) = make_float2(p10 * ip0, p11 * ip0);
    *(float2*)(P + (size_t)gB * NC + c10) = make_float2(p12 * ip1, p13 * ip1);
}

extern "C" void kernel_launch(void* const* d_in, const int* in_sizes, int n_in,
                              void* d_out, int out_size) {
    const float* z    = (const float*)d_in[0];   // (8192, 256) f32
    const float* cent = (const float*)d_in[1];   // (64, 256)   f32
    float* Q = (float*)d_out;
    float* P = Q + (size_t)NR * NC;

    cudaFuncSetAttribute(fused_kernel, cudaFuncAttributeMaxDynamicSharedMemorySize, SMEM_B);
    fused_kernel<<<NBLK, TPB, SMEM_B>>>(z, cent, Q, P);
}

// round 16
// speedup vs baseline: 1.4060x; 1.4060x over previous
#include <cuda_runtime.h>
#include <cuda_bf16.h>
#include <math.h>

#define NR   8192     // rows of z
#define HD   256      // feature dim
#define NC   64       // clusters
#define RPB  64       // rows per block
#define TPB  512      // 16 warps: 4 warp_m x 4 warp_n, warp tile m16n16
#define NBLK (NR / RPB)   // 128 blocks, one wave, 1 block/SM

// bf16 tiles [64][256], row stride 512B, XOR-swizzled; 32KB each
#define OFF_Z  0
#define OFF_C  32768
#define SMEM_B 65536

#define FXSCALE 4294967296.0f          // 2^32
#define FXINV   (1.0f / 4294967296.0f)

__device__ unsigned long long g_colfx[2][NC]; // fixed-point colsums, epoch-parity buffered
__device__ unsigned int g_start;      // start ticket counter (epoch source)
__device__ unsigned int g_arrive;     // arrival ticket counter (grid sync)

#define LDSM4(r, addr) \
    asm volatile("ldmatrix.sync.aligned.m8n8.x4.shared.b16 {%0,%1,%2,%3}, [%4];" \
        : "=r"((r)[0]), "=r"((r)[1]), "=r"((r)[2]), "=r"((r)[3]) : "r"(addr))

#define MMA16816(d, a, b0, b1) \
    asm volatile("mma.sync.aligned.m16n8k16.row.col.f32.bf16.bf16.f32 " \
        "{%0,%1,%2,%3},{%4,%5,%6,%7},{%8,%9},{%0,%1,%2,%3};" \
        : "+f"((d)[0]), "+f"((d)[1]), "+f"((d)[2]), "+f"((d)[3]) \
        : "r"((a)[0]), "r"((a)[1]), "r"((a)[2]), "r"((a)[3]), "r"(b0), "r"(b1))

__device__ __forceinline__ unsigned bf2_bits(__nv_bfloat162 h) {
    return *reinterpret_cast<unsigned*>(&h);
}
__device__ __forceinline__ float fsqrt_ap(float x) {
    float r; asm("sqrt.approx.ftz.f32 %0, %1;" : "=f"(r) : "f"(x)); return r;
}
__device__ __forceinline__ float frcp_ap(float x) {
    float r; asm("rcp.approx.ftz.f32 %0, %1;" : "=f"(r) : "f"(x)); return r;
}

__global__ void __launch_bounds__(TPB, 1)
fused_kernel(const float* __restrict__ z, const float* __restrict__ cent,
             float* __restrict__ Q, float* __restrict__ P) {
    extern __shared__ char smem[];
    char* zt = smem + OFF_Z;
    char* ct = smem + OFF_C;
    __shared__ float s_zn[RPB], s_cn[NC];
    __shared__ float s_rsp[4][RPB];    // staged row-sum partials (per wn warp-col)
    __shared__ float s_csp[4][NC];     // staged col-sum partials (per wm warp-row)
    __shared__ float s_ct[NC];         // colsum reciprocals
    __shared__ unsigned s_epoch;

    const int t = threadIdx.x;
    const unsigned sb = (unsigned)__cvta_generic_to_shared(smem);

    // epoch from monotonic start ticket (same value across all blocks of a launch)
    if (t == 0) {
        unsigned st = atomicAdd(&g_start, 1u);
        s_epoch = st / NBLK;
    }

    // ---- Phase 1: issue ALL 16 LDG.128 up front (z + centroids), then convert ----
    {
        const int row = t >> 3;
        const int l8 = t & 7;
        const float4* zg = (const float4*)(z + (size_t)blockIdx.x * RPB * HD);
        const float4* cg = (const float4*)cent;

        float4 vz[8], vc[8];
        #pragma unroll
        for (int j = 0; j < 8; j++) vz[j] = zg[row * (HD / 4) + (l8 + 8 * j)];
        #pragma unroll
        for (int j = 0; j < 8; j++) vc[j] = cg[row * (HD / 4) + (l8 + 8 * j)];

        float az = 0.f, ac = 0.f;
        #pragma unroll
        for (int j = 0; j < 8; j++) {
            const int c4 = l8 + 8 * j;
            const int byteoff = 8 * c4;
            const unsigned off = row * 512 +
                ((((byteoff >> 4) ^ (row & 7)) << 4) | (byteoff & 15));

            az = fmaf(vz[j].x, vz[j].x, az);
            az = fmaf(vz[j].y, vz[j].y, az);
            az = fmaf(vz[j].z, vz[j].z, az);
            az = fmaf(vz[j].w, vz[j].w, az);
            __nv_bfloat162 zh01 = __floats2bfloat162_rn(vz[j].x, vz[j].y);
            __nv_bfloat162 zh23 = __floats2bfloat162_rn(vz[j].z, vz[j].w);
            *(uint2*)(zt + off) = make_uint2(bf2_bits(zh01), bf2_bits(zh23));

            ac = fmaf(vc[j].x, vc[j].x, ac);
            ac = fmaf(vc[j].y, vc[j].y, ac);
            ac = fmaf(vc[j].z, vc[j].z, ac);
            ac = fmaf(vc[j].w, vc[j].w, ac);
            __nv_bfloat162 ch01 = __floats2bfloat162_rn(vc[j].x, vc[j].y);
            __nv_bfloat162 ch23 = __floats2bfloat162_rn(vc[j].z, vc[j].w);
            *(uint2*)(ct + off) = make_uint2(bf2_bits(ch01), bf2_bits(ch23));
        }
        az += __shfl_xor_sync(0xffffffffu, az, 1);
        az += __shfl_xor_sync(0xffffffffu, az, 2);
        az += __shfl_xor_sync(0xffffffffu, az, 4);
        ac += __shfl_xor_sync(0xffffffffu, ac, 1);
        ac += __shfl_xor_sync(0xffffffffu, ac, 2);
        ac += __shfl_xor_sync(0xffffffffu, ac, 4);
        if (l8 == 0) { s_zn[row] = az; s_cn[row] = ac; }
    }
    __syncthreads();   // BAR A

    // ---- Phase 2: bf16 GEMM mainloop (single-term), warp m16n16, k16/step ----
    const int lane = t & 31, wid = t >> 5;
    const int wm = wid >> 2, wn = wid & 3;
    const int tile = lane >> 3, rit = lane & 7;

    const int arow = wm * 16 + rit + 8 * (tile & 1);
    const int acb = tile >> 1;
    const unsigned abase = sb + OFF_Z + arow * 512;
    const int axor = arow & 7;

    const int brow = wn * 16 + rit + 8 * (tile >> 1);
    const int bcb = tile & 1;
    const unsigned bbase = sb + OFF_C + brow * 512;
    const int bxor = brow & 7;

    float d0[4] = {0.f, 0.f, 0.f, 0.f};   // n-half 0
    float d1[4] = {0.f, 0.f, 0.f, 0.f};   // n-half 1

    #pragma unroll
    for (int ks = 0; ks < 16; ks++) {
        const unsigned aoff = (unsigned)(((2 * ks + acb) ^ axor) << 4);
        const unsigned boff = (unsigned)(((2 * ks + bcb) ^ bxor) << 4);
        unsigned a[4], b[4];
        LDSM4(a, abase + aoff);
        LDSM4(b, bbase + boff);
        MMA16816(d0, a, b[0], b[1]);
        MMA16816(d1, a, b[2], b[3]);
    }

    // ---- Phase 3: epilogue -> Q ----
    const int gid = lane >> 2, tig = lane & 3;
    const int R0 = wm * 16 + gid, R1 = R0 + 8;
    const float znA = s_zn[R0], znB = s_zn[R1];
    const int c00 = wn * 16 + 2 * tig;
    const int c10 = c00 + 8;
    const float cnA0 = s_cn[c00], cnA1 = s_cn[c00 + 1];
    const float cnB0 = s_cn[c10], cnB1 = s_cn[c10 + 1];

    float q00 = frcp_ap(1.f + fsqrt_ap(fmaxf(fmaf(-2.f, d0[0], znA + cnA0), 0.f)));
    float q01 = frcp_ap(1.f + fsqrt_ap(fmaxf(fmaf(-2.f, d0[1], znA + cnA1), 0.f)));
    float q02 = frcp_ap(1.f + fsqrt_ap(fmaxf(fmaf(-2.f, d0[2], znB + cnA0), 0.f)));
    float q03 = frcp_ap(1.f + fsqrt_ap(fmaxf(fmaf(-2.f, d0[3], znB + cnA1), 0.f)));
    float q10 = frcp_ap(1.f + fsqrt_ap(fmaxf(fmaf(-2.f, d1[0], znA + cnB0), 0.f)));
    float q11 = frcp_ap(1.f + fsqrt_ap(fmaxf(fmaf(-2.f, d1[1], znA + cnB1), 0.f)));
    float q12 = frcp_ap(1.f + fsqrt_ap(fmaxf(fmaf(-2.f, d1[2], znB + cnB0), 0.f)));
    float q13 = frcp_ap(1.f + fsqrt_ap(fmaxf(fmaf(-2.f, d1[3], znB + cnB1), 0.f)));

    // row sums: shfl over tig lanes, then staged STS (no atomics)
    float rs0 = (q00 + q01) + (q10 + q11);
    float rs1 = (q02 + q03) + (q12 + q13);
    rs0 += __shfl_xor_sync(0xffffffffu, rs0, 1);
    rs0 += __shfl_xor_sync(0xffffffffu, rs0, 2);
    rs1 += __shfl_xor_sync(0xffffffffu, rs1, 1);
    rs1 += __shfl_xor_sync(0xffffffffu, rs1, 2);
    if (tig == 0) { s_rsp[wn][R0] = rs0; s_rsp[wn][R1] = rs1; }
    __syncthreads();   // BAR B

    const float ir0 = frcp_ap(((s_rsp[0][R0] + s_rsp[1][R0]) +
                               (s_rsp[2][R0] + s_rsp[3][R0])));
    const float ir1 = frcp_ap(((s_rsp[0][R1] + s_rsp[1][R1]) +
                               (s_rsp[2][R1] + s_rsp[3][R1])));
    q00 *= ir0; q01 *= ir0; q10 *= ir0; q11 *= ir0;
    q02 *= ir1; q03 *= ir1; q12 *= ir1; q13 *= ir1;

    const int gA = blockIdx.x * RPB + R0;
    const int gB = blockIdx.x * RPB + R1;
    *(float2*)(Q + (size_t)gA * NC + c00) = make_float2(q00, q01);
    *(float2*)(Q + (size_t)gB * NC + c00) = make_float2(q02, q03);
    *(float2*)(Q + (size_t)gA * NC + c10) = make_float2(q10, q11);
    *(float2*)(Q + (size_t)gB * NC + c10) = make_float2(q12, q13);

    // column sums: shfl over gid lanes, staged STS per wm (no atomics)
    float cA0 = q00 + q02, cA1 = q01 + q03;
    float cB0 = q10 + q12, cB1 = q11 + q13;
    #pragma unroll
    for (int m = 4; m <= 16; m <<= 1) {
        cA0 += __shfl_xor_sync(0xffffffffu, cA0, m);
        cA1 += __shfl_xor_sync(0xffffffffu, cA1, m);
        cB0 += __shfl_xor_sync(0xffffffffu, cB0, m);
        cB1 += __shfl_xor_sync(0xffffffffu, cB1, m);
    }
    if (lane < 4) {
        s_csp[wm][c00]     = cA0;
        s_csp[wm][c00 + 1] = cA1;
        s_csp[wm][c10]     = cB0;
        s_csp[wm][c10 + 1] = cB1;
    }
    __syncthreads();   // BAR C

    // deterministic fixed-point global colsum reduction: ONE atomic per column
    const unsigned buf = s_epoch & 1u;
    if (t < NC) {
        float s = (s_csp[0][t] + s_csp[1][t]) + (s_csp[2][t] + s_csp[3][t]);
        long long fx = llrintf(s * FXSCALE);
        atomicAdd(&g_colfx[buf][t], (unsigned long long)fx);
    }
    __syncthreads();   // BAR D

    // ---- single-wave grid sync (epoch ticket; release/acquire ordering) ----
    if (t == 0) {
        unsigned ticket;
        asm volatile("atom.global.add.release.gpu.u32 %0, [%1], 1;"
                     : "=r"(ticket) : "l"(&g_arrive) : "memory");
        const unsigned target = (ticket / NBLK + 1u) * NBLK;
        unsigned v;
        while (true) {
            asm volatile("ld.global.acquire.gpu.u32 %0, [%1];"
                         : "=r"(v) : "l"(&g_arrive) : "memory");
            if (v >= target) break;
            __nanosleep(32);
        }
    }
    __syncthreads();   // BAR E

    // read final colsums (512B) -> reciprocals (zeroing deferred to the end)
    if (t < NC) {
        unsigned long long v = __ldcg(&g_colfx[buf][t]);
        s_ct[t] = frcp_ap((float)v * FXINV);
    }
    __syncthreads();   // BAR F

    // ---- Phase 4: P from in-register Q ----
    const float icA0 = s_ct[c00], icA1 = s_ct[c00 + 1];
    const float icB0 = s_ct[c10], icB1 = s_ct[c10 + 1];

    float p00 = q00 * q00 * icA0, p01 = q01 * q01 * icA1;
    float p02 = q02 * q02 * icA0, p03 = q03 * q03 * icA1;
    float p10 = q10 * q10 * icB0, p11 = q11 * q11 * icB1;
    float p12 = q12 * q12 * icB0, p13 = q13 * q13 * icB1;

    float ps0 = (p00 + p01) + (p10 + p11);
    float ps1 = (p02 + p03) + (p12 + p13);
    ps0 += __shfl_xor_sync(0xffffffffu, ps0, 1);
    ps0 += __shfl_xor_sync(0xffffffffu, ps0, 2);
    ps1 += __shfl_xor_sync(0xffffffffu, ps1, 1);
    ps1 += __shfl_xor_sync(0xffffffffu, ps1, 2);
    if (tig == 0) { s_rsp[wn][R0] = ps0; s_rsp[wn][R1] = ps1; }
    __syncthreads();   // BAR G

    const float ip0 = frcp_ap(((s_rsp[0][R0] + s_rsp[1][R0]) +
                               (s_rsp[2][R0] + s_rsp[3][R0])));
    const float ip1 = frcp_ap(((s_rsp[0][R1] + s_rsp[1][R1]) +
                               (s_rsp[2][R1] + s_rsp[3][R1])));
    *(float2*)(P + (size_t)gA * NC + c00) = make_float2(p00 * ip0, p01 * ip0);
    *(float2*)(P + (size_t)gB * NC + c00) = make_float2(p02 * ip1, p03 * ip1);
    *(float2*)(P + (size_t)gA * NC + c10) = make_float2(p10 * ip0, p11 * ip0);
    *(float2*)(P + (size_t)gB * NC + c10) = make_float2(p12 * ip1, p13 * ip1);

    // zero next launch's buffer: fully off the critical path (idempotent)
    if (t < NC) g_colfx[buf ^ 1u][t] = 0ull;
}

extern "C" void kernel_launch(void* const* d_in, const int* in_sizes, int n_in,
                              void* d_out, int out_size) {
    const float* z    = (const float*)d_in[0];   // (8192, 256) f32
    const float* cent = (const float*)d_in[1];   // (64, 256)   f32
    float* Q = (float*)d_out;
    float* P = Q + (size_t)NR * NC;

    cudaFuncSetAttribute(fused_kernel, cudaFuncAttributeMaxDynamicSharedMemorySize, SMEM_B);
    fused_kernel<<<NBLK, TPB, SMEM_B>>>(z, cent, Q, P);
}